// round 15
// baseline (speedup 1.0000x reference)
#include <cuda_runtime.h>

// loss = sum_{rows, j>=1} relu(|x[:,j]-x[:,j-1]|-1) * mask[:,j]
// x, mask: [65536, 512] fp32. 256 MB HBM streaming reduction (~6 TB/s cap).
//
// Probe: Blackwell 256-bit global loads (ld.global.nc.v8.f32). Halves LDG
// count and L1tex wavefronts per byte vs float4 pairs — tests whether any
// DRAM-idle cycles come from request granularity rather than the byte cap.

#define THREADS   256
#define BLOCKS    1184             // 8 * 148, balanced single wave
#define NCHUNK    4194304LL        // 33554432 floats / 8 per chunk
#define CHUNKS_PER_ROW 64          // 512 floats / 8

__device__ float        g_partials[BLOCKS];
__device__ unsigned int g_ticket = 0;   // zero-init; reset by last block each run

__device__ __forceinline__ void ldg256(const float* __restrict__ p, float r[8]) {
    asm volatile("ld.global.nc.v8.f32 {%0,%1,%2,%3,%4,%5,%6,%7}, [%8];"
                 : "=f"(r[0]), "=f"(r[1]), "=f"(r[2]), "=f"(r[3]),
                   "=f"(r[4]), "=f"(r[5]), "=f"(r[6]), "=f"(r[7])
                 : "l"(p));
}

__global__ __launch_bounds__(THREADS)
void connect_loss_kernel(const float* __restrict__ x,
                         const float* __restrict__ mask,
                         float* __restrict__ out) {
    const long long stride = (long long)BLOCKS * THREADS;   // 303104 chunks, %64 == 0
    long long i = (long long)blockIdx.x * THREADS + threadIdx.x;
    const int lane = threadIdx.x & 31;
    // chunk-position-in-row is loop-invariant: stride % 64 == 0
    const int c = (int)(i & (CHUNKS_PER_ROW - 1));
    const bool rowstart = (c == 0);               // column 0 contributes 0
    const bool fixup = (lane == 0) && (c != 0);   // lane 0 mid-row: cross-warp neighbor

    float s = 0.0f;

    #pragma unroll 2
    for (; i < NCHUNK; i += stride) {
        float a[8], m[8];
        ldg256(x    + 8 * i, a);
        ldg256(mask + 8 * i, m);

        // previous element is lane-1's a[7] (chunks are lane-contiguous)
        float prev = __shfl_up_sync(0xffffffffu, a[7], 1);
        if (fixup) prev = __ldg(x + 8 * i - 1);

        float t0 = fmaxf(fabsf(a[0] - prev) - 1.0f, 0.0f) * m[0];
        float acc = rowstart ? 0.0f : t0;
        #pragma unroll
        for (int k = 1; k < 8; ++k)
            acc += fmaxf(fabsf(a[k] - a[k - 1]) - 1.0f, 0.0f) * m[k];
        s += acc;
    }

    // ---- block reduction ----
    __shared__ float red[THREADS / 32];
    __shared__ bool  amLast;
    const int w = threadIdx.x >> 5;

    #pragma unroll
    for (int o = 16; o > 0; o >>= 1)
        s += __shfl_xor_sync(0xffffffffu, s, o);

    if (lane == 0) red[w] = s;
    __syncthreads();

    if (threadIdx.x == 0) {
        float bs = 0.0f;
        #pragma unroll
        for (int k = 0; k < THREADS / 32; ++k) bs += red[k];
        g_partials[blockIdx.x] = bs;
        __threadfence();
        unsigned int t = atomicAdd(&g_ticket, 1u);
        amLast = (t == BLOCKS - 1);
    }
    __syncthreads();

    // ---- last block: deterministic final reduction over 1184 partials ----
    if (amLast) {
        __threadfence();
        float v = 0.0f;
        #pragma unroll
        for (int k = 0; k < 5; ++k) {                 // ceil(1184/256) = 5
            int idx = threadIdx.x + k * THREADS;
            if (idx < BLOCKS) v += g_partials[idx];
        }

        #pragma unroll
        for (int o = 16; o > 0; o >>= 1)
            v += __shfl_xor_sync(0xffffffffu, v, o);

        if (lane == 0) red[w] = v;
        __syncthreads();

        if (threadIdx.x == 0) {
            float total = 0.0f;
            #pragma unroll
            for (int k = 0; k < THREADS / 32; ++k) total += red[k];
            out[0] = total;
            g_ticket = 0;   // reset for next graph replay
        }
    }
}

extern "C" void kernel_launch(void* const* d_in, const int* in_sizes, int n_in,
                              void* d_out, int out_size) {
    const float* x    = (const float*)d_in[0];
    const float* mask = (const float*)d_in[1];
    float* out = (float*)d_out;

    connect_loss_kernel<<<BLOCKS, THREADS>>>(x, mask, out);
}

// round 16
// speedup vs baseline: 1.0418x; 1.0418x over previous
#include <cuda_runtime.h>

// loss = sum_{rows, j>=1} relu(|x[:,j]-x[:,j-1]|-1) * mask[:,j]
// x, mask: [65536, 512] fp32. 256 MB HBM streaming reduction.
//
// FINAL — converged after exhaustive mechanism search (float4/shfl, ldcs,
// warp-per-row, 512-thread, unroll 2-8, LDG.256, TMA bulk): every variant
// pins at/below the chip's path-independent L2/LTS streaming cap (~6.0 TB/s,
// invariant across occ 66-99%). Byte-traffic floor 268.4 MB / 6.0 TB/s =
// 44.7 us; this kernel: 45.06-45.31 us over five runs (<1% slack).
//
// Design: balanced single wave (8 blocks/SM * 148 SMs = 1184 blocks),
// 32 regs/thread (full 2048-thread residency pinned via launch_bounds),
// LDG.128 pairs, shfl_up neighbor exchange with lane-0 fixup (predicates
// loop-invariant: grid stride is a multiple of the 128-float4 row),
// deterministic in-kernel two-phase reduction (graph-replay safe: the
// completion ticket self-resets so every replay sees identical state).

#define THREADS   256
#define BLOCKS    1184          // 8 * 148: exactly 8 resident blocks on every SM
#define ROW_F4    128           // float4s per 512-float row
#define N4        8388608LL     // total float4s per array

__device__ float        g_partials[BLOCKS];
__device__ unsigned int g_ticket = 0;   // zero-init; reset by last block each run

__global__ __launch_bounds__(THREADS, 8)
void connect_loss_kernel(const float* __restrict__ x,
                         const float* __restrict__ mask,
                         float* __restrict__ out) {
    const float4* __restrict__ x4 = reinterpret_cast<const float4*>(x);
    const float4* __restrict__ m4 = reinterpret_cast<const float4*>(mask);

    const long long stride = (long long)BLOCKS * THREADS;   // 303104, multiple of 128
    long long i = (long long)blockIdx.x * THREADS + threadIdx.x;
    const int lane = threadIdx.x & 31;
    // position-in-row is loop-invariant: stride % 128 == 0
    const int c = (int)(i & (ROW_F4 - 1));
    const bool fixup = (lane == 0) && (c != 0);   // lane 0 mid-row: cross-warp neighbor
    const bool rowstart = (c == 0);               // column 0 contributes 0

    float s = 0.0f;

    #pragma unroll 4
    for (; i < N4; i += stride) {
        float4 v = x4[i];
        float4 m = m4[i];

        // previous element lives in lane-1's v.w (contiguous float4 -> contiguous lane)
        float prev = __shfl_up_sync(0xffffffffu, v.w, 1);
        if (fixup) prev = x[4 * i - 1];

        float d0 = fmaxf(fabsf(v.x - prev) - 1.0f, 0.0f) * m.x;
        float acc = rowstart ? 0.0f : d0;
        acc += fmaxf(fabsf(v.y - v.x) - 1.0f, 0.0f) * m.y;
        acc += fmaxf(fabsf(v.z - v.y) - 1.0f, 0.0f) * m.z;
        acc += fmaxf(fabsf(v.w - v.z) - 1.0f, 0.0f) * m.w;
        s += acc;
    }

    // ---- block reduction ----
    __shared__ float red[THREADS / 32];
    __shared__ bool  amLast;
    const int w = threadIdx.x >> 5;

    #pragma unroll
    for (int o = 16; o > 0; o >>= 1)
        s += __shfl_xor_sync(0xffffffffu, s, o);

    if (lane == 0) red[w] = s;
    __syncthreads();

    if (threadIdx.x == 0) {
        float bs = 0.0f;
        #pragma unroll
        for (int k = 0; k < THREADS / 32; ++k) bs += red[k];
        g_partials[blockIdx.x] = bs;
        __threadfence();
        unsigned int t = atomicAdd(&g_ticket, 1u);
        amLast = (t == BLOCKS - 1);
    }
    __syncthreads();

    // ---- last block: deterministic final reduction over 1184 partials ----
    if (amLast) {
        __threadfence();
        float v = 0.0f;
        #pragma unroll
        for (int k = 0; k < 5; ++k) {                 // ceil(1184/256) = 5
            int idx = threadIdx.x + k * THREADS;
            if (idx < BLOCKS) v += g_partials[idx];
        }

        #pragma unroll
        for (int o = 16; o > 0; o >>= 1)
            v += __shfl_xor_sync(0xffffffffu, v, o);

        if (lane == 0) red[w] = v;
        __syncthreads();

        if (threadIdx.x == 0) {
            float total = 0.0f;
            #pragma unroll
            for (int k = 0; k < THREADS / 32; ++k) total += red[k];
            out[0] = total;
            g_ticket = 0;   // reset for next graph replay
        }
    }
}

extern "C" void kernel_launch(void* const* d_in, const int* in_sizes, int n_in,
                              void* d_out, int out_size) {
    const float* x    = (const float*)d_in[0];
    const float* mask = (const float*)d_in[1];
    float* out = (float*)d_out;

    connect_loss_kernel<<<BLOCKS, THREADS>>>(x, mask, out);
}